// round 17
// baseline (speedup 1.0000x reference)
#include <cuda_runtime.h>
#include <cuda_bf16.h>
#include <cuda_fp16.h>
#include <cstdint>
#include <cstddef>

// ---------------------------------------------------------------------------
// Problem constants: B=2, T=2048, D=1024, NH=16, HD=64, HID=4096, CD=1024
// ---------------------------------------------------------------------------
#define BT 4096
#define DD 1024
#define HID 4096

// ---------------------------------------------------------------------------
// Device scratch (intermediates in half; residual stream fp32)
// ---------------------------------------------------------------------------
__device__ float  g_ada [2 * 6144];
__device__ float  g_xa  [(size_t)BT * DD];
__device__ __half g_h   [(size_t)BT * DD];
__device__ __half g_qkv [(size_t)BT * 3 * DD];
__device__ __half g_q   [(size_t)BT * DD];
__device__ __half g_k   [(size_t)BT * DD];
__device__ __half g_v   [(size_t)BT * DD];
__device__ __half g_attn[(size_t)BT * DD];
__device__ __half g_h2  [(size_t)BT * DD];
__device__ __half g_mid [(size_t)BT * HID];
__device__ __half g_wh  [16777216];          // qkv|proj|fc1(interleaved)|fc2 as half

// ---------------------------------------------------------------------------
// helpers
// ---------------------------------------------------------------------------
__device__ __forceinline__ uint32_t f2h2(float a, float b) {
    __half2 h = __floats2half2_rn(a, b);
    return *reinterpret_cast<uint32_t*>(&h);
}
__device__ __forceinline__ void mma_f16(float* c, const uint32_t* a, const uint32_t* b) {
    asm volatile(
        "mma.sync.aligned.m16n8k16.row.col.f32.f16.f16.f32 "
        "{%0,%1,%2,%3}, {%4,%5,%6,%7}, {%8,%9}, {%0,%1,%2,%3};"
        : "+f"(c[0]), "+f"(c[1]), "+f"(c[2]), "+f"(c[3])
        : "r"(a[0]), "r"(a[1]), "r"(a[2]), "r"(a[3]), "r"(b[0]), "r"(b[1]));
}
__device__ __forceinline__ void ldsm_x4(uint32_t* r, uint32_t smaddr) {
    asm volatile("ldmatrix.sync.aligned.m8n8.x4.shared.b16 {%0,%1,%2,%3}, [%4];"
        : "=r"(r[0]), "=r"(r[1]), "=r"(r[2]), "=r"(r[3]) : "r"(smaddr));
}

// ---------------------------------------------------------------------------
// Weight fp32 -> fp16 conversion. fc1 rows interleaved (v0,g0,v1,g1,...)
// so the GLU epilogue finds (value, gate) pairs in one thread's fragment.
// ---------------------------------------------------------------------------
__global__ void __launch_bounds__(256) w2h_kernel(
    const float* __restrict__ qkv_w, const float* __restrict__ proj_w,
    const float* __restrict__ fc1_w, const float* __restrict__ fc2_w,
    __half* __restrict__ dst)
{
    size_t i = (size_t)blockIdx.x * 256 + threadIdx.x;   // float4 index
    const float* src;
    size_t off;
    int fc1_interleave = 0;
    if (i < 786432)       { src = qkv_w;  off = i;           }
    else if (i < 1048576) { src = proj_w; off = i - 786432;  dst += (size_t)786432 * 4; }
    else if (i < 3145728) { src = fc1_w;  off = i - 1048576; dst += (size_t)1048576 * 4;
                            fc1_interleave = 1; }
    else                  { src = fc2_w;  off = i - 3145728; dst += (size_t)3145728 * 4; }
    float4 v = ((const float4*)src)[off];
    size_t doff = off;
    if (fc1_interleave) {
        size_t row = off >> 8;            // 256 float4 per row (K=1024)
        size_t c   = off & 255;
        size_t rp  = (row < 4096) ? (row << 1) : (((row - 4096) << 1) | 1);
        doff = (rp << 8) + c;
    }
    *(uint2*)(dst + doff * 4) = make_uint2(f2h2(v.x, v.y), f2h2(v.z, v.w));
}

// ---------------------------------------------------------------------------
// FP16 tensor-core GEMM: 128 threads, CTA 128x128, warp tile 64x64 (2Mx2N).
// CH: 0 -> C float (+res+gvec), 1 -> C half, 2 -> GLU epilogue (fc1):
//     even/odd interleaved N-rows are (value,gate); writes value*silu(gate)
//     as half at column cn/2 (output stride 4096).
// ---------------------------------------------------------------------------
#define HSTR 20
#define HSTAGEW (128 * HSTR)
#define GH_DSMEM (4 * HSTAGEW * 4)
template<int CH>
__global__ void __launch_bounds__(128, 2) gemm_mma(
    const __half* __restrict__ A, const __half* __restrict__ Bw,
    void* __restrict__ Cv, int M, int N, int K,
    const float* __restrict__ bias, const float* __restrict__ res,
    const float* __restrict__ gvec, int goff)
{
    extern __shared__ uint32_t sm4[];
    const uint32_t smb = (uint32_t)__cvta_generic_to_shared(sm4);
    int tid = threadIdx.x;
    int wid = tid >> 5, lane = tid & 31;
    int gr = lane >> 2, tg = lane & 3;
    int wm = wid >> 1, wn = wid & 1;
    int m0 = blockIdx.y * 128, n0 = blockIdx.x * 128;

    const __half* Ab = A + (size_t)m0 * K;
    const __half* Bb = Bw + (size_t)n0 * K;
    const int nk = K >> 5;

    float acc[4][8][4];
    #pragma unroll
    for (int i = 0; i < 4; i++)
        #pragma unroll
        for (int j = 0; j < 8; j++)
            #pragma unroll
            for (int r = 0; r < 4; r++) acc[i][j][r] = 0.0f;

    int fr[4], fcc;
    fcc = tid & 3;
    #pragma unroll
    for (int j = 0; j < 4; j++) fr[j] = (tid + j * 128) >> 2;

    uint4 pa[4], pb[4];

    #pragma unroll
    for (int j = 0; j < 4; j++) {
        pa[j] = *(const uint4*)(Ab + (size_t)fr[j] * K + fcc * 8);
        pb[j] = *(const uint4*)(Bb + (size_t)fr[j] * K + fcc * 8);
    }
    {
        uint32_t* As = sm4;
        uint32_t* Bs = sm4 + HSTAGEW;
        #pragma unroll
        for (int j = 0; j < 4; j++) {
            *(uint4*)(As + fr[j] * HSTR + fcc * 4) = pa[j];
            *(uint4*)(Bs + fr[j] * HSTR + fcc * 4) = pb[j];
        }
    }
    if (nk > 1) {
        #pragma unroll
        for (int j = 0; j < 4; j++) {
            pa[j] = *(const uint4*)(Ab + (size_t)fr[j] * K + 32 + fcc * 8);
            pb[j] = *(const uint4*)(Bb + (size_t)fr[j] * K + 32 + fcc * 8);
        }
    }
    __syncthreads();

    int am = wm * 64;
    int bn = wn * 64;

    int arow = lane & 15;
    int alo  = (lane >> 4) * 4;
    uint32_t a_off[4];
    #pragma unroll
    for (int i = 0; i < 4; i++)
        a_off[i] = (uint32_t)(((am + i * 16 + arow) * HSTR + alo) * 4);
    int brow = (lane & 7) + ((lane & 16) >> 1);
    int blo  = (lane & 8) ? 4 : 0;
    uint32_t b_off[4];
    #pragma unroll
    for (int p = 0; p < 4; p++)
        b_off[p] = (uint32_t)(((bn + p * 16 + brow) * HSTR + blo) * 4);

    for (int it = 0; it < nk; it++) {
        int s = it & 1;
        uint32_t As_b = smb + (uint32_t)(s * 2 * HSTAGEW * 4);
        uint32_t Bs_b = As_b + (uint32_t)(HSTAGEW * 4);

        #pragma unroll
        for (int ks = 0; ks < 2; ks++) {
            uint32_t af[4][4], bf[8][2];
            #pragma unroll
            for (int i = 0; i < 4; i++)
                ldsm_x4(af[i], As_b + a_off[i] + ks * 32);
            #pragma unroll
            for (int p = 0; p < 4; p++) {
                uint32_t t[4];
                ldsm_x4(t, Bs_b + b_off[p] + ks * 32);
                bf[2 * p][0] = t[0]; bf[2 * p][1] = t[1];
                bf[2 * p + 1][0] = t[2]; bf[2 * p + 1][1] = t[3];
            }
            #pragma unroll
            for (int i = 0; i < 4; i++)
                #pragma unroll
                for (int j = 0; j < 8; j++)
                    mma_f16(acc[i][j], af[i], bf[j]);
        }

        if (it + 1 < nk) {
            uint32_t* Ad = sm4 + ((it + 1) & 1) * 2 * HSTAGEW;
            uint32_t* Bd = Ad + HSTAGEW;
            #pragma unroll
            for (int j = 0; j < 4; j++) {
                *(uint4*)(Ad + fr[j] * HSTR + fcc * 4) = pa[j];
                *(uint4*)(Bd + fr[j] * HSTR + fcc * 4) = pb[j];
            }
            if (it + 2 < nk) {
                int kb = (it + 2) * 32;
                #pragma unroll
                for (int j = 0; j < 4; j++) {
                    pa[j] = *(const uint4*)(Ab + (size_t)fr[j] * K + kb + fcc * 8);
                    pb[j] = *(const uint4*)(Bb + (size_t)fr[j] * K + kb + fcc * 8);
                }
            }
            __syncthreads();
        }
    }

    #pragma unroll
    for (int i = 0; i < 4; i++) {
        #pragma unroll
        for (int j = 0; j < 8; j++) {
            int rm = m0 + am + i * 16 + gr;
            int cn = n0 + bn + j * 8 + 2 * tg;
            if (CH == 2) {
                // GLU epilogue: (c0,c1) = (value, gate) for output col cn/2
                float bv = bias[cn >> 1];
                float bg = bias[4096 + (cn >> 1)];
                #pragma unroll
                for (int half = 0; half < 2; half++) {
                    int row = rm + half * 8;
                    float v0 = acc[i][j][half * 2 + 0] + bv;
                    float v1 = acc[i][j][half * 2 + 1] + bg;
                    float m = v0 * v1 / (1.0f + __expf(-v1));
                    *((__half*)Cv + (size_t)row * 4096 + (cn >> 1)) = __float2half_rn(m);
                }
            } else {
                #pragma unroll
                for (int half = 0; half < 2; half++) {
                    int row = rm + half * 8;
                    float v0 = acc[i][j][half * 2 + 0];
                    float v1 = acc[i][j][half * 2 + 1];
                    if (bias) { v0 += bias[cn]; v1 += bias[cn + 1]; }
                    if (gvec) {
                        const float* gv = gvec + (row >> 11) * 6144 + goff + cn;
                        const float* rr = res + (size_t)row * N + cn;
                        v0 = rr[0] + gv[0] * v0;
                        v1 = rr[1] + gv[1] * v1;
                    }
                    if (CH == 1) {
                        *(__half2*)((__half*)Cv + (size_t)row * N + cn) =
                            __floats2half2_rn(v0, v1);
                    } else {
                        *(float2*)((float*)Cv + (size_t)row * N + cn) = make_float2(v0, v1);
                    }
                }
            }
        }
    }
}

// ---------------------------------------------------------------------------
// adaLN GEMV
// ---------------------------------------------------------------------------
__global__ void __launch_bounds__(256) ada_kernel(
    const float* __restrict__ cond, const float* __restrict__ W,
    const float* __restrict__ bias, float* __restrict__ ada)
{
    __shared__ float sc[2048];
    int tid = threadIdx.x;
    for (int i = tid; i < 2048; i += 256) {
        float c = cond[i];
        sc[i] = c / (1.0f + expf(-c));
    }
    __syncthreads();
    int warp = blockIdx.x * 8 + (tid >> 5);
    int lane = tid & 31;
    int b = warp / 6144;
    int col = warp % 6144;
    const float* wr = W + (size_t)col * 1024;
    const float* cr = sc + b * 1024;
    float acc = 0.0f;
    #pragma unroll
    for (int i = 0; i < 8; i++) {
        int k = lane * 4 + i * 128;
        float4 wv = *(const float4*)(wr + k);
        acc += cr[k] * wv.x + cr[k + 1] * wv.y + cr[k + 2] * wv.z + cr[k + 3] * wv.w;
    }
    #pragma unroll
    for (int o = 16; o; o >>= 1) acc += __shfl_xor_sync(0xffffffffu, acc, o);
    if (lane == 0) ada[warp] = acc + bias[col];
}

// ---------------------------------------------------------------------------
// RMSNorm + modulate: fp32 in, half out
// ---------------------------------------------------------------------------
__global__ void __launch_bounds__(256) norm_mod_kernel(
    const float* __restrict__ x, __half* __restrict__ out,
    const float* __restrict__ w, const float* __restrict__ ada,
    int sh_off, int sc_off)
{
    int row = blockIdx.x;
    int b = row >> 11;
    int tid = threadIdx.x;
    const float* xr = x + (size_t)row * 1024;
    float4 v = *(const float4*)(xr + tid * 4);
    float ss = v.x * v.x + v.y * v.y + v.z * v.z + v.w * v.w;
    #pragma unroll
    for (int o = 16; o; o >>= 1) ss += __shfl_xor_sync(0xffffffffu, ss, o);
    __shared__ float red[8];
    if ((tid & 31) == 0) red[tid >> 5] = ss;
    __syncthreads();
    float tot = 0.0f;
    #pragma unroll
    for (int i = 0; i < 8; i++) tot += red[i];
    float inv = rsqrtf(tot * (1.0f / 1024.0f) + 1e-6f);
    const float* sh = ada + b * 6144 + sh_off;
    const float* sc = ada + b * 6144 + sc_off;
    int d = tid * 4;
    float o0 = v.x * inv * w[d]     * (1.0f + sc[d])     + sh[d];
    float o1 = v.y * inv * w[d + 1] * (1.0f + sc[d + 1]) + sh[d + 1];
    float o2 = v.z * inv * w[d + 2] * (1.0f + sc[d + 2]) + sh[d + 2];
    float o3 = v.w * inv * w[d + 3] * (1.0f + sc[d + 3]) + sh[d + 3];
    *(uint2*)(out + (size_t)row * 1024 + d) =
        make_uint2(f2h2(o0, o1), f2h2(o2, o3));
}

// ---------------------------------------------------------------------------
// QK RMSNorm + RoPE + transpose: half in, half out (fast sincos/exp2)
// ---------------------------------------------------------------------------
__global__ void __launch_bounds__(256) qkv_post_kernel(
    const __half* __restrict__ qkv, __half* __restrict__ q, __half* __restrict__ k,
    __half* __restrict__ v, const float* __restrict__ qw,
    const float* __restrict__ kw, const int* __restrict__ widthp)
{
    int width = *widthp;
    int gw = blockIdx.x * 8 + (threadIdx.x >> 5);
    int lane = threadIdx.x & 31;
    int nh = gw & 15;
    int t  = (gw >> 4) & 2047;
    int b  = gw >> 15;
    const __half* src = qkv + (size_t)(b * 2048 + t) * 3072;
    int hd0 = 2 * lane;

    float2 qv = __half22float2(*(const __half2*)(src + nh * 64 + hd0));
    float2 kv = __half22float2(*(const __half2*)(src + 1024 + nh * 64 + hd0));
    __half2 vv = *(const __half2*)(src + 2048 + nh * 64 + hd0);

    float ssq = qv.x * qv.x + qv.y * qv.y;
    float ssk = kv.x * kv.x + kv.y * kv.y;
    #pragma unroll
    for (int o = 16; o; o >>= 1) {
        ssq += __shfl_xor_sync(0xffffffffu, ssq, o);
        ssk += __shfl_xor_sync(0xffffffffu, ssk, o);
    }
    float qi = rsqrtf(ssq * (1.0f / 64.0f) + 1e-6f);
    float ki = rsqrtf(ssk * (1.0f / 64.0f) + 1e-6f);
    float qx = qv.x * qi * qw[hd0], qy = qv.y * qi * qw[hd0 + 1];
    float kx = kv.x * ki * kw[hd0], ky = kv.y * ki * kw[hd0 + 1];

    int yy = t / width, xx = t % width;
    int j = lane & 15;
    float coord = (float)((lane < 16) ? yy : xx);
    float freq = exp2f((float)j * -0.8304820237218405f);
    float ang = coord * freq;
    float s, c;
    __sincosf(ang, &s, &c);
    float qox = qx * c - qy * s;
    float qoy = qy * c + qx * s;
    float kox = kx * c - ky * s;
    float koy = ky * c + kx * s;

    size_t base = ((size_t)((b * 16 + nh) * 2048 + t)) * 64 + hd0;
    *(__half2*)(q + base) = __floats2half2_rn(qox, qoy);
    *(__half2*)(k + base) = __floats2half2_rn(kox, koy);
    *(__half2*)(v + base) = vv;
}

// ---------------------------------------------------------------------------
// FP16 flash attention v3 (round-13 winner, unchanged)
// ---------------------------------------------------------------------------
#define AHSTR 36
#define AHQ   0
#define AHKV  (256 * AHSTR)
#define AHKVS (128 * AHSTR)
#define ATTH_SMEMW (AHKV + 2 * AHKVS)
__global__ void __launch_bounds__(256) attn_mma3_kernel(
    const __half* __restrict__ Q, const __half* __restrict__ K,
    const __half* __restrict__ V, __half* __restrict__ O)
{
    extern __shared__ uint32_t asm4[];
    const uint32_t smb = (uint32_t)__cvta_generic_to_shared(asm4);
    int tid = threadIdx.x;
    int wid = tid >> 5, lane = tid & 31;
    int gr = lane >> 2, tg = lane & 3;
    int qt = blockIdx.x, h = blockIdx.y, b = blockIdx.z;
    const size_t bh = ((size_t)(b * 16 + h)) * 2048 * 64;
    const int wrow = wid * 32;

    const __half2 qscale = __float2half2_rn(0.125f);

    #pragma unroll
    for (int j = 0; j < 16; j++) {
        int id = tid + j * 256;
        int r = id >> 4, c4 = (id & 15) * 4, cw = (id & 15) * 2;
        uint2 qv = *(const uint2*)(Q + bh + (size_t)(qt * 256 + r) * 64 + c4);
        __half2 a = __hmul2(*(__half2*)&qv.x, qscale);
        __half2 bq = __hmul2(*(__half2*)&qv.y, qscale);
        *(uint2*)(asm4 + AHQ + r * AHSTR + cw) =
            make_uint2(*(uint32_t*)&a, *(uint32_t*)&bq);
    }

    uint2 pk[4], pw[4];
    #pragma unroll
    for (int j = 0; j < 4; j++) {
        int id = tid + j * 256;
        int r = id >> 4, c4 = (id & 15) * 4;
        pk[j] = *(const uint2*)(K + bh + (size_t)r * 64 + c4);
        pw[j] = *(const uint2*)(V + bh + (size_t)r * 64 + c4);
    }
    {
        uint32_t* Kd = asm4 + AHKV;
        __half* Vd = (__half*)(asm4 + AHKV + 64 * AHSTR);
        #pragma unroll
        for (int j = 0; j < 4; j++) {
            int id = tid + j * 256;
            int r = id >> 4, c4 = (id & 15) * 4, cw = (id & 15) * 2;
            *(uint2*)(Kd + r * AHSTR + cw) = pk[j];
            const __half* pv = (const __half*)&pw[j];
            Vd[(c4 + 0) * (2 * AHSTR) + r] = pv[0];
            Vd[(c4 + 1) * (2 * AHSTR) + r] = pv[1];
            Vd[(c4 + 2) * (2 * AHSTR) + r] = pv[2];
            Vd[(c4 + 3) * (2 * AHSTR) + r] = pv[3];
        }
    }
    #pragma unroll
    for (int j = 0; j < 4; j++) {
        int id = tid + j * 256;
        int r = id >> 4, c4 = (id & 15) * 4;
        pk[j] = *(const uint2*)(K + bh + (size_t)(64 + r) * 64 + c4);
        pw[j] = *(const uint2*)(V + bh + (size_t)(64 + r) * 64 + c4);
    }
    __syncthreads();

    int arow = lane & 15;
    int alo  = (lane >> 4) * 4;
    uint32_t q_off[2];
    #pragma unroll
    for (int mi = 0; mi < 2; mi++)
        q_off[mi] = (uint32_t)(((wrow + mi * 16 + arow) * AHSTR + alo) * 4);
    int brow = (lane & 7) + ((lane & 16) >> 1);
    int blo  = (lane & 8) ? 4 : 0;
    uint32_t b_off[4];
    #pragma unroll
    for (int p = 0; p < 4; p++)
        b_off[p] = (uint32_t)(((p * 16 + brow) * AHSTR + blo) * 4);

    float mrow[2][2], lrow[2][2];
    #pragma unroll
    for (int mi = 0; mi < 2; mi++) {
        mrow[mi][0] = -1e30f; mrow[mi][1] = -1e30f;
        lrow[mi][0] = 0.0f;   lrow[mi][1] = 0.0f;
    }
    float o[2][8][4];
    #pragma unroll
    for (int mi = 0; mi < 2; mi++)
        #pragma unroll
        for (int j = 0; j < 8; j++)
            #pragma unroll
            for (int r = 0; r < 4; r++) o[mi][j][r] = 0.0f;

    for (int kt = 0; kt < 32; kt++) {
        uint32_t Ks_b = smb + (uint32_t)((AHKV + (kt & 1) * AHKVS) * 4);
        uint32_t Vs_b = Ks_b + (uint32_t)(64 * AHSTR * 4);

        float s[2][8][4];
        #pragma unroll
        for (int mi = 0; mi < 2; mi++)
            #pragma unroll
            for (int j = 0; j < 8; j++)
                #pragma unroll
                for (int r = 0; r < 4; r++) s[mi][j][r] = 0.0f;
        #pragma unroll
        for (int ks = 0; ks < 4; ks++) {
            uint32_t qf[2][4], bf[8][2];
            #pragma unroll
            for (int mi = 0; mi < 2; mi++)
                ldsm_x4(qf[mi], smb + q_off[mi] + ks * 32);
            #pragma unroll
            for (int p = 0; p < 4; p++) {
                uint32_t t[4];
                ldsm_x4(t, Ks_b + b_off[p] + ks * 32);
                bf[2 * p][0] = t[0]; bf[2 * p][1] = t[1];
                bf[2 * p + 1][0] = t[2]; bf[2 * p + 1][1] = t[3];
            }
            #pragma unroll
            for (int mi = 0; mi < 2; mi++)
                #pragma unroll
                for (int j = 0; j < 8; j++)
                    mma_f16(s[mi][j], qf[mi], bf[j]);
        }

        uint32_t pe[2][8][2];
        #pragma unroll
        for (int mi = 0; mi < 2; mi++) {
            float mx0 = -1e30f, mx1 = -1e30f;
            #pragma unroll
            for (int j = 0; j < 8; j++) {
                mx0 = fmaxf(mx0, fmaxf(s[mi][j][0], s[mi][j][1]));
                mx1 = fmaxf(mx1, fmaxf(s[mi][j][2], s[mi][j][3]));
            }
            #pragma unroll
            for (int off = 1; off <= 2; off <<= 1) {
                mx0 = fmaxf(mx0, __shfl_xor_sync(0xffffffffu, mx0, off));
                mx1 = fmaxf(mx1, __shfl_xor_sync(0xffffffffu, mx1, off));
            }
            float mn0 = fmaxf(mrow[mi][0], mx0), mn1 = fmaxf(mrow[mi][1], mx1);
            float cr0 = __expf(mrow[mi][0] - mn0), cr1 = __expf(mrow[mi][1] - mn1);
            mrow[mi][0] = mn0; mrow[mi][1] = mn1;
            float sum0 = 0.0f, sum1 = 0.0f;
            #pragma unroll
            for (int j = 0; j < 8; j++) {
                float e00 = __expf(s[mi][j][0] - mn0);
                float e01 = __expf(s[mi][j][1] - mn0);
                float e10 = __expf(s[mi][j][2] - mn1);
                float e11 = __expf(s[mi][j][3] - mn1);
                sum0 += e00 + e01;
                sum1 += e10 + e11;
                pe[mi][j][0] = f2h2(e00, e01);
                pe[mi][j][1] = f2h2(e10, e11);
            }
            #pragma unroll
            for (int off = 1; off <= 2; off <<= 1) {
                sum0 += __shfl_xor_sync(0xffffffffu, sum0, off);
                sum1 += __shfl_xor_sync(0xffffffffu, sum1, off);
            }
            lrow[mi][0] = lrow[mi][0] * cr0 + sum0;
            lrow[mi][1] = lrow[mi][1] * cr1 + sum1;
            #pragma unroll
            for (int j = 0; j < 8; j++) {
                o[mi][j][0] *= cr0; o[mi][j][1] *= cr0;
                o[mi][j][2] *= cr1; o[mi][j][3] *= cr1;
            }
        }

        #pragma unroll
        for (int c = 0; c < 4; c++) {
            uint32_t bf[8][2];
            #pragma unroll
            for (int p = 0; p < 4; p++) {
                uint32_t t[4];
                ldsm_x4(t, Vs_b + b_off[p] + c * 32);
                bf[2 * p][0] = t[0]; bf[2 * p][1] = t[1];
                bf[2 * p + 1][0] = t[2]; bf[2 * p + 1][1] = t[3];
            }
            #pragma unroll
            for (int mi = 0; mi < 2; mi++) {
                uint32_t af[4] = { pe[mi][2 * c][0], pe[mi][2 * c][1],
                                   pe[mi][2 * c + 1][0], pe[mi][2 * c + 1][1] };
                #pragma unroll
                for (int j = 0; j < 8; j++)
                    mma_f16(o[mi][j], af, bf[j]);
            }
        }

        if (kt + 1 < 32) {
            uint32_t* Kd = asm4 + AHKV + ((kt + 1) & 1) * AHKVS;
            __half* Vd = (__half*)(Kd + 64 * AHSTR);
            #pragma unroll
            for (int j = 0; j < 4; j++) {
                int id = tid + j * 256;
                int r = id >> 4, c4 = (id & 15) * 4, cw = (id & 15) * 2;
                *(uint2*)(Kd + r * AHSTR + cw) = pk[j];
                const __half* pv = (const __half*)&pw[j];
                Vd[(c4 + 0) * (2 * AHSTR) + r] = pv[0];
                Vd[(c4 + 1) * (2 * AHSTR) + r] = pv[1];
                Vd[(c4 + 2) * (2 * AHSTR) + r] = pv[2];
                Vd[(c4 + 3) * (2 * AHSTR) + r] = pv[3];
            }
            if (kt + 2 < 32) {
                size_t kb = bh + (size_t)(kt + 2) * 64 * 64;
                #pragma unroll
                for (int j = 0; j < 4; j++) {
                    int id = tid + j * 256;
                    int r = id >> 4, c4 = (id & 15) * 4;
                    pk[j] = *(const uint2*)(K + kb + (size_t)r * 64 + c4);
                    pw[j] = *(const uint2*)(V + kb + (size_t)r * 64 + c4);
                }
            }
            __syncthreads();
        }
    }

    #pragma unroll
    for (int mi = 0; mi < 2; mi++) {
        float inv0 = 1.0f / lrow[mi][0], inv1 = 1.0f / lrow[mi][1];
        int t0 = qt * 256 + wrow + mi * 16 + gr;
        #pragma unroll
        for (int j = 0; j < 8; j++) {
            int cn = h * 64 + j * 8 + 2 * tg;
            *(__half2*)(O + (size_t)(b * 2048 + t0) * 1024 + cn) =
                __floats2half2_rn(o[mi][j][0] * inv0, o[mi][j][1] * inv0);
            *(__half2*)(O + (size_t)(b * 2048 + t0 + 8) * 1024 + cn) =
                __floats2half2_rn(o[mi][j][2] * inv1, o[mi][j][3] * inv1);
        }
    }
}

// ---------------------------------------------------------------------------
// Launch
// ---------------------------------------------------------------------------
extern "C" void kernel_launch(void* const* d_in, const int* in_sizes, int n_in,
                              void* d_out, int out_size)
{
    const float* x        = (const float*)d_in[0];
    const float* cond     = (const float*)d_in[1];
    const float* norm1_w  = (const float*)d_in[2];
    const float* qkv_w    = (const float*)d_in[3];
    const float* q_norm_w = (const float*)d_in[4];
    const float* k_norm_w = (const float*)d_in[5];
    const float* proj_w   = (const float*)d_in[6];
    const float* proj_b   = (const float*)d_in[7];
    const float* norm2_w  = (const float*)d_in[8];
    const float* fc1_w    = (const float*)d_in[9];
    const float* fc1_b    = (const float*)d_in[10];
    const float* fc2_w    = (const float*)d_in[11];
    const float* fc2_b    = (const float*)d_in[12];
    const float* ada_w    = (const float*)d_in[13];
    const float* ada_b    = (const float*)d_in[14];
    const int*   widthp   = (const int*)d_in[16];
    float* out = (float*)d_out;

    float *p_ada, *p_xa;
    __half *p_h, *p_qkv, *p_q, *p_k, *p_v, *p_attn, *p_h2, *p_mid, *p_wh;
    cudaGetSymbolAddress((void**)&p_ada, g_ada);
    cudaGetSymbolAddress((void**)&p_xa, g_xa);
    cudaGetSymbolAddress((void**)&p_h, g_h);
    cudaGetSymbolAddress((void**)&p_qkv, g_qkv);
    cudaGetSymbolAddress((void**)&p_q, g_q);
    cudaGetSymbolAddress((void**)&p_k, g_k);
    cudaGetSymbolAddress((void**)&p_v, g_v);
    cudaGetSymbolAddress((void**)&p_attn, g_attn);
    cudaGetSymbolAddress((void**)&p_h2, g_h2);
    cudaGetSymbolAddress((void**)&p_mid, g_mid);
    cudaGetSymbolAddress((void**)&p_wh, g_wh);

    const __half* wh_qkv  = p_wh;
    const __half* wh_proj = p_wh + (size_t)3145728;
    const __half* wh_fc1  = p_wh + (size_t)4194304;
    const __half* wh_fc2  = p_wh + (size_t)12582912;

    int attn_smem = ATTH_SMEMW * 4;
    cudaFuncSetAttribute(attn_mma3_kernel, cudaFuncAttributeMaxDynamicSharedMemorySize, attn_smem);
    cudaFuncSetAttribute(gemm_mma<0>, cudaFuncAttributeMaxDynamicSharedMemorySize, GH_DSMEM);
    cudaFuncSetAttribute(gemm_mma<1>, cudaFuncAttributeMaxDynamicSharedMemorySize, GH_DSMEM);
    cudaFuncSetAttribute(gemm_mma<2>, cudaFuncAttributeMaxDynamicSharedMemorySize, GH_DSMEM);

    // 0) weights -> half (fc1 rows interleaved value/gate)
    w2h_kernel<<<16384, 256>>>(qkv_w, proj_w, fc1_w, fc2_w, p_wh);
    // 1) adaLN
    ada_kernel<<<1536, 256>>>(cond, ada_w, ada_b, p_ada);
    // 2) norm1 + modulate -> half
    norm_mod_kernel<<<4096, 256>>>(x, p_h, norm1_w, p_ada, 0, 1024);
    // 3) QKV GEMM
    gemm_mma<1><<<dim3(3072 / 128, 4096 / 128), 128, GH_DSMEM>>>(p_h, wh_qkv, p_qkv,
        4096, 3072, 1024, nullptr, nullptr, nullptr, 0);
    // 4) QK norm + RoPE + transpose (fast math)
    qkv_post_kernel<<<8192, 256>>>(p_qkv, p_q, p_k, p_v, q_norm_w, k_norm_w, widthp);
    // 5) attention
    attn_mma3_kernel<<<dim3(8, 16, 2), 256, attn_smem>>>(p_q, p_k, p_v, p_attn);
    // 6) proj GEMM + residual + gate
    gemm_mma<0><<<dim3(1024 / 128, 4096 / 128), 128, GH_DSMEM>>>(p_attn, wh_proj, p_xa,
        4096, 1024, 1024, proj_b, x, p_ada, 2 * 1024);
    // 7) norm2 + modulate -> half
    norm_mod_kernel<<<4096, 256>>>(p_xa, p_h2, norm2_w, p_ada, 3 * 1024, 4 * 1024);
    // 8) fc1 GEMM with fused GLU epilogue -> mid (mlp_act eliminated)
    gemm_mma<2><<<dim3(8192 / 128, 4096 / 128), 128, GH_DSMEM>>>(p_h2, wh_fc1, p_mid,
        4096, 8192, 1024, fc1_b, nullptr, nullptr, 0);
    // 9) fc2 GEMM + residual + gate -> out
    gemm_mma<0><<<dim3(1024 / 128, 4096 / 128), 128, GH_DSMEM>>>(p_mid, wh_fc2, out,
        4096, 1024, 4096, fc2_b, p_xa, p_ada, 5 * 1024);
}